// round 1
// baseline (speedup 1.0000x reference)
#include <cuda_runtime.h>

#define NPIX (4 * 256 * 256)   // 262144 pixels
#define CDIM 192
#define SCALE 0.17677669529663689f

// ---------------- scratch (static device arrays; no runtime allocs) --------
__device__ float g_q [NPIX * CDIM];
__device__ float g_k [NPIX * CDIM];
__device__ float g_v [NPIX * CDIM];
__device__ float g_ao[NPIX * CDIM];
__device__ float g_t3a[NPIX * 32];
__device__ float g_t3b[NPIX * 32];
__device__ float g_t5a[NPIX * 16];
__device__ float g_t5b[NPIX * 16];

// ============================================================================
// Variant A conv: implicit GEMM, BM=128 pixels x BN=64 couts, BK=16.
// 256 threads, each computes 8x4. Handles KS in {1,3,5}, NHWC input,
// OIHW weights. Optional split epilogue: cout<64 -> out0, else out1,
// written at channel base cbase into a 192-channel NHWC buffer.
// Grid: (NPIX/128, Cout/64)
// ============================================================================
template <int KS, bool RELU, bool SPLIT>
__global__ __launch_bounds__(256)
void convA(const float* __restrict__ x, const float* __restrict__ wgt,
           const float* __restrict__ bias, float* __restrict__ out0,
           float* __restrict__ out1, int Cin, int ostride, int cbase)
{
    constexpr int PAD = KS / 2;
    __shared__ float As[16][132];   // [k][m], padded row
    __shared__ float Bs[16][68];    // [k][cout]

    const int tid = threadIdx.x;
    const int tx = tid & 15;        // cout group
    const int ty = tid >> 4;        // pixel group
    const int pix0 = blockIdx.x * 128;
    const int cout0 = blockIdx.y * 64;
    const int b  = pix0 >> 16;
    const int h  = (pix0 >> 8) & 255;
    const int w0 = pix0 & 255;      // 0 or 128 (tile never crosses a row)

    float acc[8][4];
#pragma unroll
    for (int i = 0; i < 8; i++)
#pragma unroll
        for (int j = 0; j < 4; j++) acc[i][j] = 0.0f;

    for (int kh = 0; kh < KS; kh++) {
        const int hs = h + kh - PAD;
        const bool vh = ((unsigned)hs < 256u);
        for (int kw = 0; kw < KS; kw++) {
            const int dw = kw - PAD;
            const int khw = kh * KS + kw;
            for (int c0 = 0; c0 < Cin; c0 += 16) {
                // ---- load A tile: 128 pixels x 16 cin ----
#pragma unroll
                for (int r = 0; r < 8; r++) {
                    int idx = tid + r * 256;
                    int kk = idx & 15, m = idx >> 4;
                    int ws = w0 + m + dw;
                    float va = 0.0f;
                    if (vh && (unsigned)ws < 256u)
                        va = x[(size_t)((b * 256 + hs) * 256 + ws) * Cin + c0 + kk];
                    As[kk][m] = va;
                }
                // ---- load B tile: 64 couts x 16 cin ----
#pragma unroll
                for (int r = 0; r < 4; r++) {
                    int idx = tid + r * 256;
                    int kk = idx & 15, j = idx >> 4;
                    Bs[kk][j] = wgt[(size_t)(cout0 + j) * Cin * KS * KS
                                    + (c0 + kk) * KS * KS + khw];
                }
                __syncthreads();
#pragma unroll
                for (int kk = 0; kk < 16; kk++) {
                    float4 a0 = *(const float4*)&As[kk][ty * 4];
                    float4 a1 = *(const float4*)&As[kk][64 + ty * 4];
                    float4 b0 = *(const float4*)&Bs[kk][tx * 4];
                    float av[8] = {a0.x, a0.y, a0.z, a0.w, a1.x, a1.y, a1.z, a1.w};
                    float bv[4] = {b0.x, b0.y, b0.z, b0.w};
#pragma unroll
                    for (int i = 0; i < 8; i++)
#pragma unroll
                        for (int j = 0; j < 4; j++)
                            acc[i][j] += av[i] * bv[j];
                }
                __syncthreads();
            }
        }
    }

    // ---- epilogue ----
    float4 b4 = *(const float4*)&bias[cout0 + tx * 4];
    float bb[4] = {b4.x, b4.y, b4.z, b4.w};
    float* dst;
    int cb2;
    if (SPLIT) {
        if (cout0 < 64) { dst = out0; cb2 = cbase + cout0; }
        else            { dst = out1; cb2 = cbase + cout0 - 64; }
    } else { dst = out0; cb2 = cout0; }

#pragma unroll
    for (int i = 0; i < 8; i++) {
        int m = (i < 4) ? (ty * 4 + i) : (64 + ty * 4 + (i - 4));
        size_t pix = pix0 + m;
        float4 o;
        float v0 = acc[i][0] + bb[0];
        float v1 = acc[i][1] + bb[1];
        float v2 = acc[i][2] + bb[2];
        float v3 = acc[i][3] + bb[3];
        if (RELU) {
            v0 = v0 >= 0.f ? v0 : 0.2f * v0;
            v1 = v1 >= 0.f ? v1 : 0.2f * v1;
            v2 = v2 >= 0.f ? v2 : 0.2f * v2;
            v3 = v3 >= 0.f ? v3 : 0.2f * v3;
        }
        o.x = v0; o.y = v1; o.z = v2; o.w = v3;
        *(float4*)&dst[pix * (SPLIT ? 192 : ostride) + cb2 + tx * 4] = o;
    }
}

// ============================================================================
// Variant B conv: small Cout (16/32). One block per image row (256 pixels).
// Each thread holds TM pixels x COUT couts of accumulators (TM*COUT == 64).
// THREADS = 256/TM. Output stride == COUT (intermediate buffers only).
// Grid: 1024 blocks.
// ============================================================================
template <int KS, int COUT, int TM, bool RELU>
__global__ void convB(const float* __restrict__ x, const float* __restrict__ wgt,
                      const float* __restrict__ bias, float* __restrict__ out,
                      int Cin)
{
    constexpr int THREADS = 256 / TM;
    constexpr int PAD = KS / 2;
    __shared__ float As[16][257];
    __shared__ float Bs[16][COUT];

    const int tid = threadIdx.x;
    const int b = blockIdx.x >> 8;
    const int h = blockIdx.x & 255;
    const int pix0 = blockIdx.x << 8;

    float acc[TM][COUT];
#pragma unroll
    for (int i = 0; i < TM; i++)
#pragma unroll
        for (int j = 0; j < COUT; j++) acc[i][j] = 0.0f;

    for (int kh = 0; kh < KS; kh++) {
        const int hs = h + kh - PAD;
        const bool vh = ((unsigned)hs < 256u);
        for (int kw = 0; kw < KS; kw++) {
            const int dw = kw - PAD;
            const int khw = kh * KS + kw;
            for (int c0 = 0; c0 < Cin; c0 += 16) {
                // ---- A: 256 pixels x 16 cin, loaded as float4 over cin ----
                constexpr int NV = 1024 / THREADS;
#pragma unroll
                for (int r = 0; r < NV; r++) {
                    int idx4 = tid + r * THREADS;
                    int m = idx4 >> 2, q4 = idx4 & 3;
                    int ws = m + dw;
                    float4 v4 = make_float4(0.f, 0.f, 0.f, 0.f);
                    if (vh && (unsigned)ws < 256u)
                        v4 = *(const float4*)&x[(size_t)((b * 256 + hs) * 256 + ws) * Cin
                                                + c0 + q4 * 4];
                    As[q4 * 4 + 0][m] = v4.x;
                    As[q4 * 4 + 1][m] = v4.y;
                    As[q4 * 4 + 2][m] = v4.z;
                    As[q4 * 4 + 3][m] = v4.w;
                }
                // ---- B: COUT x 16 ----
                for (int idx = tid; idx < COUT * 16; idx += THREADS) {
                    int j = idx >> 4, kk = idx & 15;
                    Bs[kk][j] = wgt[(size_t)j * Cin * KS * KS + (c0 + kk) * KS * KS + khw];
                }
                __syncthreads();
#pragma unroll 4
                for (int kk = 0; kk < 16; kk++) {
                    float a[TM];
#pragma unroll
                    for (int i = 0; i < TM; i++) a[i] = As[kk][tid + i * THREADS];
#pragma unroll
                    for (int j = 0; j < COUT; j++) {
                        float bv = Bs[kk][j];
#pragma unroll
                        for (int i = 0; i < TM; i++) acc[i][j] += a[i] * bv;
                    }
                }
                __syncthreads();
            }
        }
    }

#pragma unroll
    for (int i = 0; i < TM; i++) {
        size_t pix = pix0 + tid + i * THREADS;
#pragma unroll
        for (int j = 0; j < COUT; j += 4) {
            float4 o;
            float v0 = acc[i][j + 0] + bias[j + 0];
            float v1 = acc[i][j + 1] + bias[j + 1];
            float v2 = acc[i][j + 2] + bias[j + 2];
            float v3 = acc[i][j + 3] + bias[j + 3];
            if (RELU) {
                v0 = v0 >= 0.f ? v0 : 0.2f * v0;
                v1 = v1 >= 0.f ? v1 : 0.2f * v1;
                v2 = v2 >= 0.f ? v2 : 0.2f * v2;
                v3 = v3 >= 0.f ? v3 : 0.2f * v3;
            }
            o.x = v0; o.y = v1; o.z = v2; o.w = v3;
            *(float4*)&out[pix * COUT + j] = o;
        }
    }
}

// ============================================================================
// Window attention: one 64-thread block per (window, head).
// grid = (6 heads, 4096 windows). q/k/v are NHWC (B,256,256,192).
// Output ao is (window, n, 192) = final output pixel order.
// ============================================================================
__global__ __launch_bounds__(64)
void attn_kernel(const float* __restrict__ q, const float* __restrict__ k,
                 const float* __restrict__ v, const float* __restrict__ rpb,
                 float* __restrict__ out)
{
    __shared__ float ks_[64][36];
    __shared__ float vs_[64][36];
    __shared__ float rs[225];

    const int hh = blockIdx.x;          // head 0..5
    const int wi = blockIdx.y;          // window 0..4095
    const int n  = threadIdx.x;         // row in window 0..63
    const int b  = wi >> 10;
    const int rem = wi & 1023;
    const int wh = rem >> 5, ww = rem & 31;
    const int r1 = n >> 3, c1 = n & 7;
    const int gh = wh * 8 + r1, gw = ww * 8 + c1;
    const size_t pix = (size_t)(b * 256 + gh) * 256 + gw;
    const int cb = hh * 32;

    for (int i = n; i < 225; i += 64) rs[i] = rpb[i * 6 + hh];

    float qr[32];
#pragma unroll
    for (int d4 = 0; d4 < 8; d4++) {
        float4 kv = *(const float4*)&k[pix * 192 + cb + d4 * 4];
        *(float4*)&ks_[n][d4 * 4] = kv;
        float4 vv = *(const float4*)&v[pix * 192 + cb + d4 * 4];
        *(float4*)&vs_[n][d4 * 4] = vv;
        float4 qv = *(const float4*)&q[pix * 192 + cb + d4 * 4];
        qr[d4 * 4 + 0] = qv.x * SCALE;
        qr[d4 * 4 + 1] = qv.y * SCALE;
        qr[d4 * 4 + 2] = qv.z * SCALE;
        qr[d4 * 4 + 3] = qv.w * SCALE;
    }
    __syncthreads();

    float s[64];
    float mx = -1e30f;
#pragma unroll
    for (int m = 0; m < 64; m++) {
        float dot = 0.f;
#pragma unroll
        for (int d4 = 0; d4 < 8; d4++) {
            float4 kk4 = *(const float4*)&ks_[m][d4 * 4];
            dot += qr[d4 * 4 + 0] * kk4.x;
            dot += qr[d4 * 4 + 1] * kk4.y;
            dot += qr[d4 * 4 + 2] * kk4.z;
            dot += qr[d4 * 4 + 3] * kk4.w;
        }
        int dr = r1 - (m >> 3) + 7;
        int dc = c1 - (m & 7) + 7;
        dot += rs[dr * 15 + dc];
        s[m] = dot;
        mx = fmaxf(mx, dot);
    }
    float sum = 0.f;
#pragma unroll
    for (int m = 0; m < 64; m++) {
        s[m] = __expf(s[m] - mx);
        sum += s[m];
    }
    const float inv = 1.0f / sum;

    float accv[32];
#pragma unroll
    for (int d = 0; d < 32; d++) accv[d] = 0.f;
#pragma unroll
    for (int m = 0; m < 64; m++) {
        float p = s[m];
#pragma unroll
        for (int d4 = 0; d4 < 8; d4++) {
            float4 vv = *(const float4*)&vs_[m][d4 * 4];
            accv[d4 * 4 + 0] += p * vv.x;
            accv[d4 * 4 + 1] += p * vv.y;
            accv[d4 * 4 + 2] += p * vv.z;
            accv[d4 * 4 + 3] += p * vv.w;
        }
    }
    const size_t opix = (size_t)wi * 64 + n;
#pragma unroll
    for (int d4 = 0; d4 < 8; d4++) {
        float4 o;
        o.x = accv[d4 * 4 + 0] * inv;
        o.y = accv[d4 * 4 + 1] * inv;
        o.z = accv[d4 * 4 + 2] * inv;
        o.w = accv[d4 * 4 + 3] * inv;
        *(float4*)&out[opix * 192 + cb + d4 * 4] = o;
    }
}

// ============================================================================
extern "C" void kernel_launch(void* const* d_in, const int* in_sizes, int n_in,
                              void* d_out, int out_size)
{
    const float* x      = (const float*)d_in[0];
    const float* v_w    = (const float*)d_in[1];
    const float* v_b    = (const float*)d_in[2];
    const float* qk1_w  = (const float*)d_in[3];
    const float* qk1_b  = (const float*)d_in[4];
    const float* qk3_w1 = (const float*)d_in[5];
    const float* qk3_b1 = (const float*)d_in[6];
    const float* qk3_w2 = (const float*)d_in[7];
    const float* qk3_b2 = (const float*)d_in[8];
    const float* qk3_w3 = (const float*)d_in[9];
    const float* qk3_b3 = (const float*)d_in[10];
    const float* qk5_w1 = (const float*)d_in[11];
    const float* qk5_b1 = (const float*)d_in[12];
    const float* qk5_w2 = (const float*)d_in[13];
    const float* qk5_b2 = (const float*)d_in[14];
    const float* qk5_w3 = (const float*)d_in[15];
    const float* qk5_b3 = (const float*)d_in[16];
    const float* rpb    = (const float*)d_in[17];
    const float* proj_w = (const float*)d_in[18];
    const float* proj_b = (const float*)d_in[19];
    float* out = (float*)d_out;

    float *q, *k, *v, *ao, *t3a, *t3b, *t5a, *t5b;
    cudaGetSymbolAddress((void**)&q,   g_q);
    cudaGetSymbolAddress((void**)&k,   g_k);
    cudaGetSymbolAddress((void**)&v,   g_v);
    cudaGetSymbolAddress((void**)&ao,  g_ao);
    cudaGetSymbolAddress((void**)&t3a, g_t3a);
    cudaGetSymbolAddress((void**)&t3b, g_t3b);
    cudaGetSymbolAddress((void**)&t5a, g_t5a);
    cudaGetSymbolAddress((void**)&t5b, g_t5b);

    const int PT = NPIX / 128;   // 2048 pixel tiles for variant A

    // v = conv1x1(x) -> g_v (192ch, stride 192)
    convA<1, false, false><<<dim3(PT, 3), 256>>>(x, v_w, v_b, v, nullptr, 192, 192, 0);
    // qk1 -> split into q[0:64), k[0:64)
    convA<1, false, true><<<dim3(PT, 2), 256>>>(x, qk1_w, qk1_b, q, k, 192, 192, 0);
    // scale-3 branch
    convB<3, 32, 2, true><<<1024, 128>>>(x,   qk3_w1, qk3_b1, t3a, 192);
    convB<1, 32, 2, true><<<1024, 128>>>(t3a, qk3_w2, qk3_b2, t3b, 32);
    convA<3, false, true><<<dim3(PT, 2), 256>>>(t3b, qk3_w3, qk3_b3, q, k, 32, 192, 64);
    // scale-5 branch
    convB<5, 16, 4, true><<<1024, 64>>>(x,   qk5_w1, qk5_b1, t5a, 192);
    convB<1, 16, 4, true><<<1024, 64>>>(t5a, qk5_w2, qk5_b2, t5b, 16);
    convA<5, false, true><<<dim3(PT, 2), 256>>>(t5b, qk5_w3, qk5_b3, q, k, 16, 192, 128);
    // window attention -> ao (window-ordered pixels)
    attn_kernel<<<dim3(6, 4096), 64>>>(q, k, v, rpb, ao);
    // output projection straight into d_out
    convA<1, false, false><<<dim3(PT, 3), 256>>>(ao, proj_w, proj_b, out, nullptr, 192, 192, 0);
}

// round 3
// speedup vs baseline: 1.0711x; 1.0711x over previous
#include <cuda_runtime.h>
#include <cstdint>

#define NPIX (4 * 256 * 256)   // 262144 pixels
#define CDIM 192
#define SCALE 0.17677669529663689f

// ---------------- scratch (static device arrays; no runtime allocs) --------
__device__ float g_q [NPIX * CDIM];
__device__ float g_k [NPIX * CDIM];
__device__ float g_v [NPIX * CDIM];
__device__ float g_ao[NPIX * CDIM];
__device__ float g_t3a[NPIX * 32];
__device__ float g_t3b[NPIX * 32];
__device__ float g_t5a[NPIX * 16];
__device__ float g_t5b[NPIX * 16];

__device__ __forceinline__ uint32_t f2tf(float x) {
    uint32_t u;
    asm("cvt.rna.tf32.f32 %0, %1;" : "=r"(u) : "f"(x));
    return u;
}

__device__ __forceinline__ void mma_tf32_16x8x8(float* c, const uint32_t* a,
                                                const uint32_t* b) {
    asm volatile(
        "mma.sync.aligned.m16n8k8.row.col.f32.tf32.tf32.f32 "
        "{%0,%1,%2,%3}, {%4,%5,%6,%7}, {%8,%9}, {%0,%1,%2,%3};"
        : "+f"(c[0]), "+f"(c[1]), "+f"(c[2]), "+f"(c[3])
        : "r"(a[0]), "r"(a[1]), "r"(a[2]), "r"(a[3]), "r"(b[0]), "r"(b[1]));
}

// ============================================================================
// 1x1 conv as tf32 mma.sync GEMM.
// C[M=NPIX, N] = X[M,192] * W[N,192]^T + bias.  BM=128, BN=64, BK=16.
// 128 threads = 4 warps in 2x2; each warp does 64x32 (4x4 m16n8k8 tiles).
// grid = (NPIX/128, Ncols/64).  Output stride 192 (NHWC channel slice).
// SPLIT: n-block 0 -> out0 at cbase, n-block 1 -> out1 at cbase.
// ============================================================================
template <bool SPLIT>
__global__ __launch_bounds__(128)
void gemm1x1(const float* __restrict__ X, const float* __restrict__ Wt,
             const float* __restrict__ bias, float* __restrict__ out0,
             float* __restrict__ out1, int cbase)
{
    __shared__ uint32_t As[16][132];
    __shared__ uint32_t Bs[16][68];

    const int tid  = threadIdx.x;
    const int lane = tid & 31;
    const int warp = tid >> 5;
    const int grp  = lane >> 2;       // 0..7
    const int thr4 = lane & 3;        // 0..3
    const int mo = (warp >> 1) * 64;  // warp M offset in block
    const int no = (warp & 1) * 32;   // warp N offset in block
    const int pix0 = blockIdx.x * 128;
    const int n0 = blockIdx.y * 64;

    float acc[4][4][4];
#pragma unroll
    for (int i = 0; i < 4; i++)
#pragma unroll
        for (int j = 0; j < 4; j++)
#pragma unroll
            for (int r = 0; r < 4; r++) acc[i][j][r] = 0.0f;

    for (int c0 = 0; c0 < 192; c0 += 16) {
        // ---- stage A: 128 pixels x 16 ch.  thread tid -> pixel tid ----
        {
            const float4* src = (const float4*)(X + (size_t)(pix0 + tid) * 192 + c0);
#pragma unroll
            for (int r = 0; r < 4; r++) {
                float4 v4 = src[r];
                As[r * 4 + 0][tid] = f2tf(v4.x);
                As[r * 4 + 1][tid] = f2tf(v4.y);
                As[r * 4 + 2][tid] = f2tf(v4.z);
                As[r * 4 + 3][tid] = f2tf(v4.w);
            }
        }
        // ---- stage B: 64 couts x 16 ch ----
        {
#pragma unroll
            for (int r = 0; r < 2; r++) {
                int idx = tid + r * 128;        // 0..255
                int j = idx >> 2, q = idx & 3;
                float4 v4 = *(const float4*)(Wt + (size_t)(n0 + j) * 192 + c0 + q * 4);
                Bs[q * 4 + 0][j] = f2tf(v4.x);
                Bs[q * 4 + 1][j] = f2tf(v4.y);
                Bs[q * 4 + 2][j] = f2tf(v4.z);
                Bs[q * 4 + 3][j] = f2tf(v4.w);
            }
        }
        __syncthreads();

#pragma unroll
        for (int ks = 0; ks < 16; ks += 8) {
            uint32_t a[4][4], b[4][2];
#pragma unroll
            for (int mi = 0; mi < 4; mi++) {
                int row = mo + mi * 16 + grp;
                a[mi][0] = As[ks + thr4][row];
                a[mi][1] = As[ks + thr4][row + 8];
                a[mi][2] = As[ks + thr4 + 4][row];
                a[mi][3] = As[ks + thr4 + 4][row + 8];
            }
#pragma unroll
            for (int ni = 0; ni < 4; ni++) {
                int col = no + ni * 8 + grp;
                b[ni][0] = Bs[ks + thr4][col];
                b[ni][1] = Bs[ks + thr4 + 4][col];
            }
#pragma unroll
            for (int mi = 0; mi < 4; mi++)
#pragma unroll
                for (int ni = 0; ni < 4; ni++)
                    mma_tf32_16x8x8(acc[mi][ni], a[mi], b[ni]);
        }
        __syncthreads();
    }

    // ---- epilogue ----
    float* dst;
    int cb;
    if (SPLIT) {
        if (n0 < 64) { dst = out0; cb = cbase; }
        else         { dst = out1; cb = cbase; }
    } else { dst = out0; cb = n0; }

#pragma unroll
    for (int mi = 0; mi < 4; mi++) {
        size_t r0 = (size_t)(pix0 + mo + mi * 16 + grp);
        size_t r1 = r0 + 8;
#pragma unroll
        for (int ni = 0; ni < 4; ni++) {
            int colL = no + ni * 8 + 2 * thr4;           // local col in [0,64)
            float b0 = __ldg(&bias[n0 + colL]);
            float b1 = __ldg(&bias[n0 + colL + 1]);
            float2 o0 = make_float2(acc[mi][ni][0] + b0, acc[mi][ni][1] + b1);
            float2 o1 = make_float2(acc[mi][ni][2] + b0, acc[mi][ni][3] + b1);
            *(float2*)&dst[r0 * 192 + cb + colL] = o0;
            *(float2*)&dst[r1 * 192 + cb + colL] = o1;
        }
    }
}

// ============================================================================
// Variant A conv (fp32 scalar): KS in {3,5}, big split convs.
// ============================================================================
template <int KS, bool RELU, bool SPLIT>
__global__ __launch_bounds__(256)
void convA(const float* __restrict__ x, const float* __restrict__ wgt,
           const float* __restrict__ bias, float* __restrict__ out0,
           float* __restrict__ out1, int Cin, int ostride, int cbase)
{
    constexpr int PAD = KS / 2;
    __shared__ float As[16][132];
    __shared__ float Bs[16][68];

    const int tid = threadIdx.x;
    const int tx = tid & 15;
    const int ty = tid >> 4;
    const int pix0 = blockIdx.x * 128;
    const int cout0 = blockIdx.y * 64;
    const int b  = pix0 >> 16;
    const int h  = (pix0 >> 8) & 255;
    const int w0 = pix0 & 255;

    float acc[8][4];
#pragma unroll
    for (int i = 0; i < 8; i++)
#pragma unroll
        for (int j = 0; j < 4; j++) acc[i][j] = 0.0f;

    for (int kh = 0; kh < KS; kh++) {
        const int hs = h + kh - PAD;
        const bool vh = ((unsigned)hs < 256u);
        for (int kw = 0; kw < KS; kw++) {
            const int dw = kw - PAD;
            const int khw = kh * KS + kw;
            for (int c0 = 0; c0 < Cin; c0 += 16) {
#pragma unroll
                for (int r = 0; r < 8; r++) {
                    int idx = tid + r * 256;
                    int kk = idx & 15, m = idx >> 4;
                    int ws = w0 + m + dw;
                    float va = 0.0f;
                    if (vh && (unsigned)ws < 256u)
                        va = x[(size_t)((b * 256 + hs) * 256 + ws) * Cin + c0 + kk];
                    As[kk][m] = va;
                }
#pragma unroll
                for (int r = 0; r < 4; r++) {
                    int idx = tid + r * 256;
                    int kk = idx & 15, j = idx >> 4;
                    Bs[kk][j] = wgt[(size_t)(cout0 + j) * Cin * KS * KS
                                    + (c0 + kk) * KS * KS + khw];
                }
                __syncthreads();
#pragma unroll
                for (int kk = 0; kk < 16; kk++) {
                    float4 a0 = *(const float4*)&As[kk][ty * 4];
                    float4 a1 = *(const float4*)&As[kk][64 + ty * 4];
                    float4 b0 = *(const float4*)&Bs[kk][tx * 4];
                    float av[8] = {a0.x, a0.y, a0.z, a0.w, a1.x, a1.y, a1.z, a1.w};
                    float bv[4] = {b0.x, b0.y, b0.z, b0.w};
#pragma unroll
                    for (int i = 0; i < 8; i++)
#pragma unroll
                        for (int j = 0; j < 4; j++)
                            acc[i][j] += av[i] * bv[j];
                }
                __syncthreads();
            }
        }
    }

    float4 b4 = *(const float4*)&bias[cout0 + tx * 4];
    float bb[4] = {b4.x, b4.y, b4.z, b4.w};
    float* dst;
    int cb2;
    if (SPLIT) {
        if (cout0 < 64) { dst = out0; cb2 = cbase + cout0; }
        else            { dst = out1; cb2 = cbase + cout0 - 64; }
    } else { dst = out0; cb2 = cout0; }

#pragma unroll
    for (int i = 0; i < 8; i++) {
        int m = (i < 4) ? (ty * 4 + i) : (64 + ty * 4 + (i - 4));
        size_t pix = pix0 + m;
        float4 o;
        float v0 = acc[i][0] + bb[0];
        float v1 = acc[i][1] + bb[1];
        float v2 = acc[i][2] + bb[2];
        float v3 = acc[i][3] + bb[3];
        if (RELU) {
            v0 = v0 >= 0.f ? v0 : 0.2f * v0;
            v1 = v1 >= 0.f ? v1 : 0.2f * v1;
            v2 = v2 >= 0.f ? v2 : 0.2f * v2;
            v3 = v3 >= 0.f ? v3 : 0.2f * v3;
        }
        o.x = v0; o.y = v1; o.z = v2; o.w = v3;
        *(float4*)&dst[pix * (SPLIT ? 192 : ostride) + cb2 + tx * 4] = o;
    }
}

// ============================================================================
// Variant B conv (fp32 scalar): small Cout (16/32).
// ============================================================================
template <int KS, int COUT, int TM, bool RELU>
__global__ void convB(const float* __restrict__ x, const float* __restrict__ wgt,
                      const float* __restrict__ bias, float* __restrict__ out,
                      int Cin)
{
    constexpr int THREADS = 256 / TM;
    constexpr int PAD = KS / 2;
    __shared__ float As[16][257];
    __shared__ float Bs[16][COUT];

    const int tid = threadIdx.x;
    const int b = blockIdx.x >> 8;
    const int h = blockIdx.x & 255;
    const int pix0 = blockIdx.x << 8;

    float acc[TM][COUT];
#pragma unroll
    for (int i = 0; i < TM; i++)
#pragma unroll
        for (int j = 0; j < COUT; j++) acc[i][j] = 0.0f;

    for (int kh = 0; kh < KS; kh++) {
        const int hs = h + kh - PAD;
        const bool vh = ((unsigned)hs < 256u);
        for (int kw = 0; kw < KS; kw++) {
            const int dw = kw - PAD;
            const int khw = kh * KS + kw;
            for (int c0 = 0; c0 < Cin; c0 += 16) {
                constexpr int NV = 1024 / THREADS;
#pragma unroll
                for (int r = 0; r < NV; r++) {
                    int idx4 = tid + r * THREADS;
                    int m = idx4 >> 2, q4 = idx4 & 3;
                    int ws = m + dw;
                    float4 v4 = make_float4(0.f, 0.f, 0.f, 0.f);
                    if (vh && (unsigned)ws < 256u)
                        v4 = *(const float4*)&x[(size_t)((b * 256 + hs) * 256 + ws) * Cin
                                                + c0 + q4 * 4];
                    As[q4 * 4 + 0][m] = v4.x;
                    As[q4 * 4 + 1][m] = v4.y;
                    As[q4 * 4 + 2][m] = v4.z;
                    As[q4 * 4 + 3][m] = v4.w;
                }
                for (int idx = tid; idx < COUT * 16; idx += THREADS) {
                    int j = idx >> 4, kk = idx & 15;
                    Bs[kk][j] = wgt[(size_t)j * Cin * KS * KS + (c0 + kk) * KS * KS + khw];
                }
                __syncthreads();
#pragma unroll 4
                for (int kk = 0; kk < 16; kk++) {
                    float a[TM];
#pragma unroll
                    for (int i = 0; i < TM; i++) a[i] = As[kk][tid + i * THREADS];
#pragma unroll
                    for (int j = 0; j < COUT; j++) {
                        float bv = Bs[kk][j];
#pragma unroll
                        for (int i = 0; i < TM; i++) acc[i][j] += a[i] * bv;
                    }
                }
                __syncthreads();
            }
        }
    }

#pragma unroll
    for (int i = 0; i < TM; i++) {
        size_t pix = pix0 + tid + i * THREADS;
#pragma unroll
        for (int j = 0; j < COUT; j += 4) {
            float4 o;
            float v0 = acc[i][j + 0] + bias[j + 0];
            float v1 = acc[i][j + 1] + bias[j + 1];
            float v2 = acc[i][j + 2] + bias[j + 2];
            float v3 = acc[i][j + 3] + bias[j + 3];
            if (RELU) {
                v0 = v0 >= 0.f ? v0 : 0.2f * v0;
                v1 = v1 >= 0.f ? v1 : 0.2f * v1;
                v2 = v2 >= 0.f ? v2 : 0.2f * v2;
                v3 = v3 >= 0.f ? v3 : 0.2f * v3;
            }
            o.x = v0; o.y = v1; o.z = v2; o.w = v3;
            *(float4*)&out[pix * COUT + j] = o;
        }
    }
}

// ============================================================================
// Window attention (unchanged)
// ============================================================================
__global__ __launch_bounds__(64)
void attn_kernel(const float* __restrict__ q, const float* __restrict__ k,
                 const float* __restrict__ v, const float* __restrict__ rpb,
                 float* __restrict__ out)
{
    __shared__ float ks_[64][36];
    __shared__ float vs_[64][36];
    __shared__ float rs[225];

    const int hh = blockIdx.x;
    const int wi = blockIdx.y;
    const int n  = threadIdx.x;
    const int b  = wi >> 10;
    const int rem = wi & 1023;
    const int wh = rem >> 5, ww = rem & 31;
    const int r1 = n >> 3, c1 = n & 7;
    const int gh = wh * 8 + r1, gw = ww * 8 + c1;
    const size_t pix = (size_t)(b * 256 + gh) * 256 + gw;
    const int cb = hh * 32;

    for (int i = n; i < 225; i += 64) rs[i] = rpb[i * 6 + hh];

    float qr[32];
#pragma unroll
    for (int d4 = 0; d4 < 8; d4++) {
        float4 kv = *(const float4*)&k[pix * 192 + cb + d4 * 4];
        *(float4*)&ks_[n][d4 * 4] = kv;
        float4 vv = *(const float4*)&v[pix * 192 + cb + d4 * 4];
        *(float4*)&vs_[n][d4 * 4] = vv;
        float4 qv = *(const float4*)&q[pix * 192 + cb + d4 * 4];
        qr[d4 * 4 + 0] = qv.x * SCALE;
        qr[d4 * 4 + 1] = qv.y * SCALE;
        qr[d4 * 4 + 2] = qv.z * SCALE;
        qr[d4 * 4 + 3] = qv.w * SCALE;
    }
    __syncthreads();

    float s[64];
    float mx = -1e30f;
#pragma unroll
    for (int m = 0; m < 64; m++) {
        float dot = 0.f;
#pragma unroll
        for (int d4 = 0; d4 < 8; d4++) {
            float4 kk4 = *(const float4*)&ks_[m][d4 * 4];
            dot += qr[d4 * 4 + 0] * kk4.x;
            dot += qr[d4 * 4 + 1] * kk4.y;
            dot += qr[d4 * 4 + 2] * kk4.z;
            dot += qr[d4 * 4 + 3] * kk4.w;
        }
        int dr = r1 - (m >> 3) + 7;
        int dc = c1 - (m & 7) + 7;
        dot += rs[dr * 15 + dc];
        s[m] = dot;
        mx = fmaxf(mx, dot);
    }
    float sum = 0.f;
#pragma unroll
    for (int m = 0; m < 64; m++) {
        s[m] = __expf(s[m] - mx);
        sum += s[m];
    }
    const float inv = 1.0f / sum;

    float accv[32];
#pragma unroll
    for (int d = 0; d < 32; d++) accv[d] = 0.f;
#pragma unroll
    for (int m = 0; m < 64; m++) {
        float p = s[m];
#pragma unroll
        for (int d4 = 0; d4 < 8; d4++) {
            float4 vv = *(const float4*)&vs_[m][d4 * 4];
            accv[d4 * 4 + 0] += p * vv.x;
            accv[d4 * 4 + 1] += p * vv.y;
            accv[d4 * 4 + 2] += p * vv.z;
            accv[d4 * 4 + 3] += p * vv.w;
        }
    }
    const size_t opix = (size_t)wi * 64 + n;
#pragma unroll
    for (int d4 = 0; d4 < 8; d4++) {
        float4 o;
        o.x = accv[d4 * 4 + 0] * inv;
        o.y = accv[d4 * 4 + 1] * inv;
        o.z = accv[d4 * 4 + 2] * inv;
        o.w = accv[d4 * 4 + 3] * inv;
        *(float4*)&out[opix * 192 + cb + d4 * 4] = o;
    }
}

// ============================================================================
extern "C" void kernel_launch(void* const* d_in, const int* in_sizes, int n_in,
                              void* d_out, int out_size)
{
    const float* x      = (const float*)d_in[0];
    const float* v_w    = (const float*)d_in[1];
    const float* v_b    = (const float*)d_in[2];
    const float* qk1_w  = (const float*)d_in[3];
    const float* qk1_b  = (const float*)d_in[4];
    const float* qk3_w1 = (const float*)d_in[5];
    const float* qk3_b1 = (const float*)d_in[6];
    const float* qk3_w2 = (const float*)d_in[7];
    const float* qk3_b2 = (const float*)d_in[8];
    const float* qk3_w3 = (const float*)d_in[9];
    const float* qk3_b3 = (const float*)d_in[10];
    const float* qk5_w1 = (const float*)d_in[11];
    const float* qk5_b1 = (const float*)d_in[12];
    const float* qk5_w2 = (const float*)d_in[13];
    const float* qk5_b2 = (const float*)d_in[14];
    const float* qk5_w3 = (const float*)d_in[15];
    const float* qk5_b3 = (const float*)d_in[16];
    const float* rpb    = (const float*)d_in[17];
    const float* proj_w = (const float*)d_in[18];
    const float* proj_b = (const float*)d_in[19];
    float* out = (float*)d_out;

    float *q, *k, *v, *ao, *t3a, *t3b, *t5a, *t5b;
    cudaGetSymbolAddress((void**)&q,   g_q);
    cudaGetSymbolAddress((void**)&k,   g_k);
    cudaGetSymbolAddress((void**)&v,   g_v);
    cudaGetSymbolAddress((void**)&ao,  g_ao);
    cudaGetSymbolAddress((void**)&t3a, g_t3a);
    cudaGetSymbolAddress((void**)&t3b, g_t3b);
    cudaGetSymbolAddress((void**)&t5a, g_t5a);
    cudaGetSymbolAddress((void**)&t5b, g_t5b);

    const int PT = NPIX / 128;   // 2048 pixel tiles

    // v = conv1x1(x): tf32 mma GEMM, N=192 in three 64-col blocks
    gemm1x1<false><<<dim3(PT, 3), 128>>>(x, v_w, v_b, v, nullptr, 0);
    // qk1: tf32 mma GEMM, N=128, split q/k at cbase 0
    gemm1x1<true><<<dim3(PT, 2), 128>>>(x, qk1_w, qk1_b, q, k, 0);
    // scale-3 branch (fp32 scalar)
    convB<3, 32, 2, true><<<1024, 128>>>(x,   qk3_w1, qk3_b1, t3a, 192);
    convB<1, 32, 2, true><<<1024, 128>>>(t3a, qk3_w2, qk3_b2, t3b, 32);
    convA<3, false, true><<<dim3(PT, 2), 256>>>(t3b, qk3_w3, qk3_b3, q, k, 32, 192, 64);
    // scale-5 branch (fp32 scalar)
    convB<5, 16, 4, true><<<1024, 64>>>(x,   qk5_w1, qk5_b1, t5a, 192);
    convB<1, 16, 4, true><<<1024, 64>>>(t5a, qk5_w2, qk5_b2, t5b, 16);
    convA<5, false, true><<<dim3(PT, 2), 256>>>(t5b, qk5_w3, qk5_b3, q, k, 16, 192, 128);
    // window attention
    attn_kernel<<<dim3(6, 4096), 64>>>(q, k, v, rpb, ao);
    // output projection: tf32 mma GEMM straight into d_out
    gemm1x1<false><<<dim3(PT, 3), 128>>>(ao, proj_w, proj_b, out, nullptr, 0);
}

// round 4
// speedup vs baseline: 2.1100x; 1.9699x over previous
#include <cuda_runtime.h>
#include <cstdint>

#define NPIX (4 * 256 * 256)   // 262144 pixels
#define CDIM 192
#define SCALE 0.17677669529663689f

// ---------------- scratch (static device arrays; no runtime allocs) --------
__device__ float g_q [NPIX * CDIM];
__device__ float g_k [NPIX * CDIM];
__device__ float g_v [NPIX * CDIM];
__device__ float g_ao[NPIX * CDIM];
__device__ float g_t3a[NPIX * 32];
__device__ float g_t3b[NPIX * 32];
__device__ float g_t5a[NPIX * 16];
__device__ float g_t5b[NPIX * 16];

__device__ __forceinline__ uint32_t f2tf(float x) {
    uint32_t u;
    asm("cvt.rna.tf32.f32 %0, %1;" : "=r"(u) : "f"(x));
    return u;
}

__device__ __forceinline__ void mma_tf32_16x8x8(float* c, const uint32_t* a,
                                                const uint32_t* b) {
    asm volatile(
        "mma.sync.aligned.m16n8k8.row.col.f32.tf32.tf32.f32 "
        "{%0,%1,%2,%3}, {%4,%5,%6,%7}, {%8,%9}, {%0,%1,%2,%3};"
        : "+f"(c[0]), "+f"(c[1]), "+f"(c[2]), "+f"(c[3])
        : "r"(a[0]), "r"(a[1]), "r"(a[2]), "r"(a[3]), "r"(b[0]), "r"(b[1]));
}

// ============================================================================
// Unified implicit-GEMM conv on tf32 mma.sync.
// One CTA = one image row (256 output pixels) x BN output channels.
// 256 threads / 8 warps. A slab (256+2*PAD pixels x 16 cin) staged once per
// (kh, c0); kw taps are shifted SMEM reads. B staged for all kw per (kh, c0).
// grid = (1024 rows, Ncols/BN).
// SPLIT: n-block 0 -> out0, n-block 1 -> out1 at channel cbase, stride 192.
// Non-split: out0 with channel base n0, stride OSTR.
// ============================================================================
template <int KS, int CIN, int BN, int OSTR, bool RELU, bool SPLIT>
__global__ __launch_bounds__(256)
void conv_mma(const float* __restrict__ X, const float* __restrict__ Wt,
              const float* __restrict__ bias, float* __restrict__ out0,
              float* __restrict__ out1, int cbase)
{
    constexpr int PAD = KS / 2;
    constexpr int AS_S = 264;          // A smem stride (%32 == 8)
    constexpr int BS_S = KS * BN + 8;  // B smem stride (%32 in {8,24})
    __shared__ uint32_t As[16][AS_S];
    __shared__ uint32_t Bs[16][BS_S];

    const int tid = threadIdx.x;
    const int lane = tid & 31, warp = tid >> 5;
    const int grp = lane >> 2, thr4 = lane & 3;

    constexpr int NW = (BN == 64) ? 2 : 1;   // warps along N
    constexpr int MW = 8 / NW;               // warps along M
    constexpr int WROWS = 256 / MW;          // 64 or 32
    constexpr int WCOLS = BN / NW;           // 32 or 16
    constexpr int MI = WROWS / 16;           // 4 or 2
    constexpr int NI = WCOLS / 8;            // 4 or 2
    const int mo = (NW == 2 ? (warp >> 1) : warp) * WROWS;
    const int no = (NW == 2 ? (warp & 1) : 0) * WCOLS;

    const int row = blockIdx.x;              // b*256 + h
    const int h = row & 255;
    const int pixbase = row << 8;
    const int n0 = blockIdx.y * BN;

    float acc[MI][NI][4];
#pragma unroll
    for (int i = 0; i < MI; i++)
#pragma unroll
        for (int j = 0; j < NI; j++)
#pragma unroll
            for (int r = 0; r < 4; r++) acc[i][j][r] = 0.0f;

    for (int kh = 0; kh < KS; kh++) {
        const int hs = h + kh - PAD;
        const bool vh = ((unsigned)hs < 256u);
        const int spix = (row - h + hs) << 8;   // pixel index of (b, hs, 0)
        for (int c0 = 0; c0 < CIN; c0 += 16) {
            // ---- stage A: (256 + 2*PAD) pixels x 16 cin; col p -> ws=p-PAD --
            {
                const int ws = tid - PAD;
                const bool ok = vh && ((unsigned)ws < 256u);
                const float* src = X + (size_t)(spix + ws) * CIN + c0;
#pragma unroll
                for (int r = 0; r < 4; r++) {
                    float4 v4 = make_float4(0.f, 0.f, 0.f, 0.f);
                    if (ok) v4 = *(const float4*)(src + r * 4);
                    As[r * 4 + 0][tid] = f2tf(v4.x);
                    As[r * 4 + 1][tid] = f2tf(v4.y);
                    As[r * 4 + 2][tid] = f2tf(v4.z);
                    As[r * 4 + 3][tid] = f2tf(v4.w);
                }
                if (PAD > 0 && tid < 2 * PAD) {
                    const int p2 = 256 + tid;
                    const int ws2 = p2 - PAD;
                    const bool ok2 = vh && ((unsigned)ws2 < 256u);
                    const float* src2 = X + (size_t)(spix + ws2) * CIN + c0;
#pragma unroll
                    for (int r = 0; r < 4; r++) {
                        float4 v4 = make_float4(0.f, 0.f, 0.f, 0.f);
                        if (ok2) v4 = *(const float4*)(src2 + r * 4);
                        As[r * 4 + 0][p2] = f2tf(v4.x);
                        As[r * 4 + 1][p2] = f2tf(v4.y);
                        As[r * 4 + 2][p2] = f2tf(v4.z);
                        As[r * 4 + 3][p2] = f2tf(v4.w);
                    }
                }
            }
            // ---- stage B: BN couts x 16 cin x KS kw taps ----
            {
                constexpr int TOT = KS * BN * 16;
#pragma unroll
                for (int it = 0; it < TOT / 256; it++) {
                    int idx = tid + it * 256;
                    int kw2 = idx / (BN * 16);
                    int rem = idx - kw2 * (BN * 16);
                    int j = rem >> 4, kk = rem & 15;
                    Bs[kk][kw2 * BN + j] =
                        f2tf(Wt[(size_t)(n0 + j) * (CIN * KS * KS)
                                + (c0 + kk) * (KS * KS) + kh * KS + kw2]);
                }
            }
            __syncthreads();

#pragma unroll
            for (int kw = 0; kw < KS; kw++) {
#pragma unroll
                for (int ks = 0; ks < 16; ks += 8) {
                    uint32_t a[MI][4], b[NI][2];
#pragma unroll
                    for (int mi = 0; mi < MI; mi++) {
                        int col = mo + mi * 16 + grp + kw;
                        a[mi][0] = As[ks + thr4][col];
                        a[mi][1] = As[ks + thr4][col + 8];
                        a[mi][2] = As[ks + thr4 + 4][col];
                        a[mi][3] = As[ks + thr4 + 4][col + 8];
                    }
#pragma unroll
                    for (int ni = 0; ni < NI; ni++) {
                        int bc = kw * BN + no + ni * 8 + grp;
                        b[ni][0] = Bs[ks + thr4][bc];
                        b[ni][1] = Bs[ks + thr4 + 4][bc];
                    }
#pragma unroll
                    for (int mi = 0; mi < MI; mi++)
#pragma unroll
                        for (int ni = 0; ni < NI; ni++)
                            mma_tf32_16x8x8(acc[mi][ni], a[mi], b[ni]);
                }
            }
            __syncthreads();
        }
    }

    // ---- epilogue ----
    float* dst;
    int cb, stride;
    if (SPLIT) {
        if (n0 < 64) { dst = out0; } else { dst = out1; }
        cb = cbase; stride = 192;
    } else { dst = out0; cb = n0; stride = OSTR; }

#pragma unroll
    for (int mi = 0; mi < MI; mi++) {
        size_t r0 = (size_t)(pixbase + mo + mi * 16 + grp);
        size_t r1 = r0 + 8;
#pragma unroll
        for (int ni = 0; ni < NI; ni++) {
            int colL = no + ni * 8 + 2 * thr4;
            float b0 = __ldg(&bias[n0 + colL]);
            float b1 = __ldg(&bias[n0 + colL + 1]);
            float v00 = acc[mi][ni][0] + b0, v01 = acc[mi][ni][1] + b1;
            float v10 = acc[mi][ni][2] + b0, v11 = acc[mi][ni][3] + b1;
            if (RELU) {
                v00 = v00 >= 0.f ? v00 : 0.2f * v00;
                v01 = v01 >= 0.f ? v01 : 0.2f * v01;
                v10 = v10 >= 0.f ? v10 : 0.2f * v10;
                v11 = v11 >= 0.f ? v11 : 0.2f * v11;
            }
            *(float2*)&dst[r0 * stride + cb + colL] = make_float2(v00, v01);
            *(float2*)&dst[r1 * stride + cb + colL] = make_float2(v10, v11);
        }
    }
}

// ============================================================================
// Variant B conv (fp32 scalar): tiny 1x1 convs (32->32, 16->16).
// ============================================================================
template <int KS, int COUT, int TM, bool RELU>
__global__ void convB(const float* __restrict__ x, const float* __restrict__ wgt,
                      const float* __restrict__ bias, float* __restrict__ out,
                      int Cin)
{
    constexpr int THREADS = 256 / TM;
    constexpr int PAD = KS / 2;
    __shared__ float As[16][257];
    __shared__ float Bs[16][COUT];

    const int tid = threadIdx.x;
    const int b = blockIdx.x >> 8;
    const int h = blockIdx.x & 255;
    const int pix0 = blockIdx.x << 8;

    float acc[TM][COUT];
#pragma unroll
    for (int i = 0; i < TM; i++)
#pragma unroll
        for (int j = 0; j < COUT; j++) acc[i][j] = 0.0f;

    for (int kh = 0; kh < KS; kh++) {
        const int hs = h + kh - PAD;
        const bool vh = ((unsigned)hs < 256u);
        for (int kw = 0; kw < KS; kw++) {
            const int dw = kw - PAD;
            const int khw = kh * KS + kw;
            for (int c0 = 0; c0 < Cin; c0 += 16) {
                constexpr int NV = 1024 / THREADS;
#pragma unroll
                for (int r = 0; r < NV; r++) {
                    int idx4 = tid + r * THREADS;
                    int m = idx4 >> 2, q4 = idx4 & 3;
                    int ws = m + dw;
                    float4 v4 = make_float4(0.f, 0.f, 0.f, 0.f);
                    if (vh && (unsigned)ws < 256u)
                        v4 = *(const float4*)&x[(size_t)((b * 256 + hs) * 256 + ws) * Cin
                                                + c0 + q4 * 4];
                    As[q4 * 4 + 0][m] = v4.x;
                    As[q4 * 4 + 1][m] = v4.y;
                    As[q4 * 4 + 2][m] = v4.z;
                    As[q4 * 4 + 3][m] = v4.w;
                }
                for (int idx = tid; idx < COUT * 16; idx += THREADS) {
                    int j = idx >> 4, kk = idx & 15;
                    Bs[kk][j] = wgt[(size_t)j * Cin * KS * KS + (c0 + kk) * KS * KS + khw];
                }
                __syncthreads();
#pragma unroll 4
                for (int kk = 0; kk < 16; kk++) {
                    float a[TM];
#pragma unroll
                    for (int i = 0; i < TM; i++) a[i] = As[kk][tid + i * THREADS];
#pragma unroll
                    for (int j = 0; j < COUT; j++) {
                        float bv = Bs[kk][j];
#pragma unroll
                        for (int i = 0; i < TM; i++) acc[i][j] += a[i] * bv;
                    }
                }
                __syncthreads();
            }
        }
    }

#pragma unroll
    for (int i = 0; i < TM; i++) {
        size_t pix = pix0 + tid + i * THREADS;
#pragma unroll
        for (int j = 0; j < COUT; j += 4) {
            float4 o;
            float v0 = acc[i][j + 0] + bias[j + 0];
            float v1 = acc[i][j + 1] + bias[j + 1];
            float v2 = acc[i][j + 2] + bias[j + 2];
            float v3 = acc[i][j + 3] + bias[j + 3];
            if (RELU) {
                v0 = v0 >= 0.f ? v0 : 0.2f * v0;
                v1 = v1 >= 0.f ? v1 : 0.2f * v1;
                v2 = v2 >= 0.f ? v2 : 0.2f * v2;
                v3 = v3 >= 0.f ? v3 : 0.2f * v3;
            }
            o.x = v0; o.y = v1; o.z = v2; o.w = v3;
            *(float4*)&out[pix * COUT + j] = o;
        }
    }
}

// ============================================================================
// Window attention (unchanged)
// ============================================================================
__global__ __launch_bounds__(64)
void attn_kernel(const float* __restrict__ q, const float* __restrict__ k,
                 const float* __restrict__ v, const float* __restrict__ rpb,
                 float* __restrict__ out)
{
    __shared__ float ks_[64][36];
    __shared__ float vs_[64][36];
    __shared__ float rs[225];

    const int hh = blockIdx.x;
    const int wi = blockIdx.y;
    const int n  = threadIdx.x;
    const int b  = wi >> 10;
    const int rem = wi & 1023;
    const int wh = rem >> 5, ww = rem & 31;
    const int r1 = n >> 3, c1 = n & 7;
    const int gh = wh * 8 + r1, gw = ww * 8 + c1;
    const size_t pix = (size_t)(b * 256 + gh) * 256 + gw;
    const int cb = hh * 32;

    for (int i = n; i < 225; i += 64) rs[i] = rpb[i * 6 + hh];

    float qr[32];
#pragma unroll
    for (int d4 = 0; d4 < 8; d4++) {
        float4 kv = *(const float4*)&k[pix * 192 + cb + d4 * 4];
        *(float4*)&ks_[n][d4 * 4] = kv;
        float4 vv = *(const float4*)&v[pix * 192 + cb + d4 * 4];
        *(float4*)&vs_[n][d4 * 4] = vv;
        float4 qv = *(const float4*)&q[pix * 192 + cb + d4 * 4];
        qr[d4 * 4 + 0] = qv.x * SCALE;
        qr[d4 * 4 + 1] = qv.y * SCALE;
        qr[d4 * 4 + 2] = qv.z * SCALE;
        qr[d4 * 4 + 3] = qv.w * SCALE;
    }
    __syncthreads();

    float s[64];
    float mx = -1e30f;
#pragma unroll
    for (int m = 0; m < 64; m++) {
        float dot = 0.f;
#pragma unroll
        for (int d4 = 0; d4 < 8; d4++) {
            float4 kk4 = *(const float4*)&ks_[m][d4 * 4];
            dot += qr[d4 * 4 + 0] * kk4.x;
            dot += qr[d4 * 4 + 1] * kk4.y;
            dot += qr[d4 * 4 + 2] * kk4.z;
            dot += qr[d4 * 4 + 3] * kk4.w;
        }
        int dr = r1 - (m >> 3) + 7;
        int dc = c1 - (m & 7) + 7;
        dot += rs[dr * 15 + dc];
        s[m] = dot;
        mx = fmaxf(mx, dot);
    }
    float sum = 0.f;
#pragma unroll
    for (int m = 0; m < 64; m++) {
        s[m] = __expf(s[m] - mx);
        sum += s[m];
    }
    const float inv = 1.0f / sum;

    float accv[32];
#pragma unroll
    for (int d = 0; d < 32; d++) accv[d] = 0.f;
#pragma unroll
    for (int m = 0; m < 64; m++) {
        float p = s[m];
#pragma unroll
        for (int d4 = 0; d4 < 8; d4++) {
            float4 vv = *(const float4*)&vs_[m][d4 * 4];
            accv[d4 * 4 + 0] += p * vv.x;
            accv[d4 * 4 + 1] += p * vv.y;
            accv[d4 * 4 + 2] += p * vv.z;
            accv[d4 * 4 + 3] += p * vv.w;
        }
    }
    const size_t opix = (size_t)wi * 64 + n;
#pragma unroll
    for (int d4 = 0; d4 < 8; d4++) {
        float4 o;
        o.x = accv[d4 * 4 + 0] * inv;
        o.y = accv[d4 * 4 + 1] * inv;
        o.z = accv[d4 * 4 + 2] * inv;
        o.w = accv[d4 * 4 + 3] * inv;
        *(float4*)&out[opix * 192 + cb + d4 * 4] = o;
    }
}

// ============================================================================
extern "C" void kernel_launch(void* const* d_in, const int* in_sizes, int n_in,
                              void* d_out, int out_size)
{
    const float* x      = (const float*)d_in[0];
    const float* v_w    = (const float*)d_in[1];
    const float* v_b    = (const float*)d_in[2];
    const float* qk1_w  = (const float*)d_in[3];
    const float* qk1_b  = (const float*)d_in[4];
    const float* qk3_w1 = (const float*)d_in[5];
    const float* qk3_b1 = (const float*)d_in[6];
    const float* qk3_w2 = (const float*)d_in[7];
    const float* qk3_b2 = (const float*)d_in[8];
    const float* qk3_w3 = (const float*)d_in[9];
    const float* qk3_b3 = (const float*)d_in[10];
    const float* qk5_w1 = (const float*)d_in[11];
    const float* qk5_b1 = (const float*)d_in[12];
    const float* qk5_w2 = (const float*)d_in[13];
    const float* qk5_b2 = (const float*)d_in[14];
    const float* qk5_w3 = (const float*)d_in[15];
    const float* qk5_b3 = (const float*)d_in[16];
    const float* rpb    = (const float*)d_in[17];
    const float* proj_w = (const float*)d_in[18];
    const float* proj_b = (const float*)d_in[19];
    float* out = (float*)d_out;

    float *q, *k, *v, *ao, *t3a, *t3b, *t5a, *t5b;
    cudaGetSymbolAddress((void**)&q,   g_q);
    cudaGetSymbolAddress((void**)&k,   g_k);
    cudaGetSymbolAddress((void**)&v,   g_v);
    cudaGetSymbolAddress((void**)&ao,  g_ao);
    cudaGetSymbolAddress((void**)&t3a, g_t3a);
    cudaGetSymbolAddress((void**)&t3b, g_t3b);
    cudaGetSymbolAddress((void**)&t5a, g_t5a);
    cudaGetSymbolAddress((void**)&t5b, g_t5b);

    // v = conv1x1(x): N=192 in three 64-col blocks, stride 192
    conv_mma<1, 192, 64, 192, false, false><<<dim3(1024, 3), 256>>>(
        x, v_w, v_b, v, nullptr, 0);
    // qk1: N=128, split q/k at cbase 0
    conv_mma<1, 192, 64, 192, false, true><<<dim3(1024, 2), 256>>>(
        x, qk1_w, qk1_b, q, k, 0);
    // scale-3 branch
    conv_mma<3, 192, 32, 32, true, false><<<dim3(1024, 1), 256>>>(
        x, qk3_w1, qk3_b1, t3a, nullptr, 0);
    convB<1, 32, 2, true><<<1024, 128>>>(t3a, qk3_w2, qk3_b2, t3b, 32);
    conv_mma<3, 32, 64, 192, false, true><<<dim3(1024, 2), 256>>>(
        t3b, qk3_w3, qk3_b3, q, k, 64);
    // scale-5 branch
    conv_mma<5, 192, 16, 16, true, false><<<dim3(1024, 1), 256>>>(
        x, qk5_w1, qk5_b1, t5a, nullptr, 0);
    convB<1, 16, 4, true><<<1024, 64>>>(t5a, qk5_w2, qk5_b2, t5b, 16);
    conv_mma<5, 16, 64, 192, false, true><<<dim3(1024, 2), 256>>>(
        t5b, qk5_w3, qk5_b3, q, k, 128);
    // window attention
    attn_kernel<<<dim3(6, 4096), 64>>>(q, k, v, rpb, ao);
    // output projection straight into d_out
    conv_mma<1, 192, 64, 192, false, false><<<dim3(1024, 3), 256>>>(
        ao, proj_w, proj_b, out, nullptr, 0);
}

// round 5
// speedup vs baseline: 2.2500x; 1.0664x over previous
#include <cuda_runtime.h>
#include <cuda_fp16.h>
#include <cstdint>

#define NPIX (4 * 256 * 256)   // 262144 pixels
#define CDIM 192
#define SCALE 0.17677669529663689f

// ---------------- scratch (static device arrays; no runtime allocs) --------
__device__ float g_q [NPIX * CDIM];
__device__ float g_k [NPIX * CDIM];
__device__ float g_v [NPIX * CDIM];
__device__ float g_ao[NPIX * CDIM];
__device__ float g_t3a[NPIX * 32];
__device__ float g_t3b[NPIX * 32];
__device__ float g_t5a[NPIX * 16];
__device__ float g_t5b[NPIX * 16];

__device__ __forceinline__ uint32_t pack_h2(float a, float b) {
    __half2 h = __floats2half2_rn(a, b);
    return *(uint32_t*)&h;
}

__device__ __forceinline__ void mma_f16_16x8x16(float* c, const uint32_t* a,
                                                const uint32_t* b) {
    asm volatile(
        "mma.sync.aligned.m16n8k16.row.col.f32.f16.f16.f32 "
        "{%0,%1,%2,%3}, {%4,%5,%6,%7}, {%8,%9}, {%0,%1,%2,%3};"
        : "+f"(c[0]), "+f"(c[1]), "+f"(c[2]), "+f"(c[3])
        : "r"(a[0]), "r"(a[1]), "r"(a[2]), "r"(a[3]), "r"(b[0]), "r"(b[1]));
}

// ============================================================================
// Unified implicit-GEMM conv on fp16 mma.sync (fp32 accumulate).
// One CTA = one image row (256 output pixels) x BN output channels.
// 256 threads / 8 warps. A slab (256+2*PAD pixels x 16 cin, half2-packed)
// staged once per (kh, c0); kw taps are shifted SMEM reads.
// grid = (1024 rows, Ncols/BN).
// SPLIT: n-block 0 -> out0, n-block 1 -> out1 at channel cbase, stride 192.
// ============================================================================
template <int KS, int CIN, int BN, int OSTR, bool RELU, bool SPLIT>
__global__ __launch_bounds__(256)
void conv_mma(const float* __restrict__ X, const float* __restrict__ Wt,
              const float* __restrict__ bias, float* __restrict__ out0,
              float* __restrict__ out1, int cbase)
{
    constexpr int PAD = KS / 2;
    constexpr int AS_S = 264;          // A smem stride (uint32), %32 == 8
    constexpr int BS_S = KS * BN + 8;  // B smem stride, %32 in {8,24}
    __shared__ uint32_t As[8][AS_S];   // [k/2][pixel] half2 (k, k+1)
    __shared__ uint32_t Bs[8][BS_S];   // [k/2][kw*BN + cout]

    const int tid = threadIdx.x;
    const int lane = tid & 31, warp = tid >> 5;
    const int grp = lane >> 2, thr4 = lane & 3;

    constexpr int NW = (BN == 64) ? 2 : 1;
    constexpr int MW = 8 / NW;
    constexpr int WROWS = 256 / MW;          // 64 or 32
    constexpr int WCOLS = BN / NW;           // 32 or 16
    constexpr int MI = WROWS / 16;
    constexpr int NI = WCOLS / 8;
    const int mo = (NW == 2 ? (warp >> 1) : warp) * WROWS;
    const int no = (NW == 2 ? (warp & 1) : 0) * WCOLS;

    const int row = blockIdx.x;              // b*256 + h
    const int h = row & 255;
    const int pixbase = row << 8;
    const int n0 = blockIdx.y * BN;

    float acc[MI][NI][4];
#pragma unroll
    for (int i = 0; i < MI; i++)
#pragma unroll
        for (int j = 0; j < NI; j++)
#pragma unroll
            for (int r = 0; r < 4; r++) acc[i][j][r] = 0.0f;

    for (int kh = 0; kh < KS; kh++) {
        const int hs = h + kh - PAD;
        const bool vh = ((unsigned)hs < 256u);
        const int spix = (row - h + hs) << 8;
        for (int c0 = 0; c0 < CIN; c0 += 16) {
            // ---- stage A: (256 + 2*PAD) pixels x 16 cin; col p -> ws=p-PAD --
            {
                const int ws = tid - PAD;
                const bool ok = vh && ((unsigned)ws < 256u);
                const float* src = X + (size_t)(spix + ws) * CIN + c0;
#pragma unroll
                for (int r = 0; r < 4; r++) {
                    float4 v4 = make_float4(0.f, 0.f, 0.f, 0.f);
                    if (ok) v4 = *(const float4*)(src + r * 4);
                    As[r * 2 + 0][tid] = pack_h2(v4.x, v4.y);
                    As[r * 2 + 1][tid] = pack_h2(v4.z, v4.w);
                }
                if (PAD > 0 && tid < 2 * PAD) {
                    const int p2 = 256 + tid;
                    const int ws2 = p2 - PAD;
                    const bool ok2 = vh && ((unsigned)ws2 < 256u);
                    const float* src2 = X + (size_t)(spix + ws2) * CIN + c0;
#pragma unroll
                    for (int r = 0; r < 4; r++) {
                        float4 v4 = make_float4(0.f, 0.f, 0.f, 0.f);
                        if (ok2) v4 = *(const float4*)(src2 + r * 4);
                        As[r * 2 + 0][p2] = pack_h2(v4.x, v4.y);
                        As[r * 2 + 1][p2] = pack_h2(v4.z, v4.w);
                    }
                }
            }
            // ---- stage B: BN couts x 8 k-pairs x KS kw taps ----
            {
                constexpr int TOT = KS * BN * 8;
                for (int idx = tid; idx < TOT; idx += 256) {
                    int kw2 = idx / (BN * 8);
                    int rem = idx - kw2 * (BN * 8);
                    int j = rem >> 3, kp = rem & 7;
                    const float* wsrc = Wt + (size_t)(n0 + j) * (CIN * KS * KS)
                                        + (c0 + 2 * kp) * (KS * KS) + kh * KS + kw2;
                    Bs[kp][kw2 * BN + j] = pack_h2(wsrc[0], wsrc[KS * KS]);
                }
            }
            __syncthreads();

#pragma unroll
            for (int kw = 0; kw < KS; kw++) {
                uint32_t a[MI][4], b[NI][2];
#pragma unroll
                for (int mi = 0; mi < MI; mi++) {
                    int col = mo + mi * 16 + grp + kw;
                    a[mi][0] = As[thr4][col];
                    a[mi][1] = As[thr4][col + 8];
                    a[mi][2] = As[thr4 + 4][col];
                    a[mi][3] = As[thr4 + 4][col + 8];
                }
#pragma unroll
                for (int ni = 0; ni < NI; ni++) {
                    int bc = kw * BN + no + ni * 8 + grp;
                    b[ni][0] = Bs[thr4][bc];
                    b[ni][1] = Bs[thr4 + 4][bc];
                }
#pragma unroll
                for (int mi = 0; mi < MI; mi++)
#pragma unroll
                    for (int ni = 0; ni < NI; ni++)
                        mma_f16_16x8x16(acc[mi][ni], a[mi], b[ni]);
            }
            __syncthreads();
        }
    }

    // ---- epilogue ----
    float* dst;
    int cb, stride;
    if (SPLIT) {
        if (n0 < 64) { dst = out0; } else { dst = out1; }
        cb = cbase; stride = 192;
    } else { dst = out0; cb = n0; stride = OSTR; }

#pragma unroll
    for (int mi = 0; mi < MI; mi++) {
        size_t r0 = (size_t)(pixbase + mo + mi * 16 + grp);
        size_t r1 = r0 + 8;
#pragma unroll
        for (int ni = 0; ni < NI; ni++) {
            int colL = no + ni * 8 + 2 * thr4;
            float b0 = __ldg(&bias[n0 + colL]);
            float b1 = __ldg(&bias[n0 + colL + 1]);
            float v00 = acc[mi][ni][0] + b0, v01 = acc[mi][ni][1] + b1;
            float v10 = acc[mi][ni][2] + b0, v11 = acc[mi][ni][3] + b1;
            if (RELU) {
                v00 = v00 >= 0.f ? v00 : 0.2f * v00;
                v01 = v01 >= 0.f ? v01 : 0.2f * v01;
                v10 = v10 >= 0.f ? v10 : 0.2f * v10;
                v11 = v11 >= 0.f ? v11 : 0.2f * v11;
            }
            *(float2*)&dst[r0 * stride + cb + colL] = make_float2(v00, v01);
            *(float2*)&dst[r1 * stride + cb + colL] = make_float2(v10, v11);
        }
    }
}

// ============================================================================
// Variant B conv (fp32 scalar): tiny 1x1 convs (32->32, 16->16).
// ============================================================================
template <int KS, int COUT, int TM, bool RELU>
__global__ void convB(const float* __restrict__ x, const float* __restrict__ wgt,
                      const float* __restrict__ bias, float* __restrict__ out,
                      int Cin)
{
    constexpr int THREADS = 256 / TM;
    constexpr int PAD = KS / 2;
    __shared__ float As[16][257];
    __shared__ float Bs[16][COUT];

    const int tid = threadIdx.x;
    const int b = blockIdx.x >> 8;
    const int h = blockIdx.x & 255;
    const int pix0 = blockIdx.x << 8;

    float acc[TM][COUT];
#pragma unroll
    for (int i = 0; i < TM; i++)
#pragma unroll
        for (int j = 0; j < COUT; j++) acc[i][j] = 0.0f;

    for (int kh = 0; kh < KS; kh++) {
        const int hs = h + kh - PAD;
        const bool vh = ((unsigned)hs < 256u);
        for (int kw = 0; kw < KS; kw++) {
            const int dw = kw - PAD;
            const int khw = kh * KS + kw;
            for (int c0 = 0; c0 < Cin; c0 += 16) {
                constexpr int NV = 1024 / THREADS;
#pragma unroll
                for (int r = 0; r < NV; r++) {
                    int idx4 = tid + r * THREADS;
                    int m = idx4 >> 2, q4 = idx4 & 3;
                    int ws = m + dw;
                    float4 v4 = make_float4(0.f, 0.f, 0.f, 0.f);
                    if (vh && (unsigned)ws < 256u)
                        v4 = *(const float4*)&x[(size_t)((b * 256 + hs) * 256 + ws) * Cin
                                                + c0 + q4 * 4];
                    As[q4 * 4 + 0][m] = v4.x;
                    As[q4 * 4 + 1][m] = v4.y;
                    As[q4 * 4 + 2][m] = v4.z;
                    As[q4 * 4 + 3][m] = v4.w;
                }
                for (int idx = tid; idx < COUT * 16; idx += THREADS) {
                    int j = idx >> 4, kk = idx & 15;
                    Bs[kk][j] = wgt[(size_t)j * Cin * KS * KS + (c0 + kk) * KS * KS + khw];
                }
                __syncthreads();
#pragma unroll 4
                for (int kk = 0; kk < 16; kk++) {
                    float a[TM];
#pragma unroll
                    for (int i = 0; i < TM; i++) a[i] = As[kk][tid + i * THREADS];
#pragma unroll
                    for (int j = 0; j < COUT; j++) {
                        float bv = Bs[kk][j];
#pragma unroll
                        for (int i = 0; i < TM; i++) acc[i][j] += a[i] * bv;
                    }
                }
                __syncthreads();
            }
        }
    }

#pragma unroll
    for (int i = 0; i < TM; i++) {
        size_t pix = pix0 + tid + i * THREADS;
#pragma unroll
        for (int j = 0; j < COUT; j += 4) {
            float4 o;
            float v0 = acc[i][j + 0] + bias[j + 0];
            float v1 = acc[i][j + 1] + bias[j + 1];
            float v2 = acc[i][j + 2] + bias[j + 2];
            float v3 = acc[i][j + 3] + bias[j + 3];
            if (RELU) {
                v0 = v0 >= 0.f ? v0 : 0.2f * v0;
                v1 = v1 >= 0.f ? v1 : 0.2f * v1;
                v2 = v2 >= 0.f ? v2 : 0.2f * v2;
                v3 = v3 >= 0.f ? v3 : 0.2f * v3;
            }
            o.x = v0; o.y = v1; o.z = v2; o.w = v3;
            *(float4*)&out[pix * COUT + j] = o;
        }
    }
}

// ============================================================================
// Window attention (unchanged)
// ============================================================================
__global__ __launch_bounds__(64)
void attn_kernel(const float* __restrict__ q, const float* __restrict__ k,
                 const float* __restrict__ v, const float* __restrict__ rpb,
                 float* __restrict__ out)
{
    __shared__ float ks_[64][36];
    __shared__ float vs_[64][36];
    __shared__ float rs[225];

    const int hh = blockIdx.x;
    const int wi = blockIdx.y;
    const int n  = threadIdx.x;
    const int b  = wi >> 10;
    const int rem = wi & 1023;
    const int wh = rem >> 5, ww = rem & 31;
    const int r1 = n >> 3, c1 = n & 7;
    const int gh = wh * 8 + r1, gw = ww * 8 + c1;
    const size_t pix = (size_t)(b * 256 + gh) * 256 + gw;
    const int cb = hh * 32;

    for (int i = n; i < 225; i += 64) rs[i] = rpb[i * 6 + hh];

    float qr[32];
#pragma unroll
    for (int d4 = 0; d4 < 8; d4++) {
        float4 kv = *(const float4*)&k[pix * 192 + cb + d4 * 4];
        *(float4*)&ks_[n][d4 * 4] = kv;
        float4 vv = *(const float4*)&v[pix * 192 + cb + d4 * 4];
        *(float4*)&vs_[n][d4 * 4] = vv;
        float4 qv = *(const float4*)&q[pix * 192 + cb + d4 * 4];
        qr[d4 * 4 + 0] = qv.x * SCALE;
        qr[d4 * 4 + 1] = qv.y * SCALE;
        qr[d4 * 4 + 2] = qv.z * SCALE;
        qr[d4 * 4 + 3] = qv.w * SCALE;
    }
    __syncthreads();

    float s[64];
    float mx = -1e30f;
#pragma unroll
    for (int m = 0; m < 64; m++) {
        float dot = 0.f;
#pragma unroll
        for (int d4 = 0; d4 < 8; d4++) {
            float4 kk4 = *(const float4*)&ks_[m][d4 * 4];
            dot += qr[d4 * 4 + 0] * kk4.x;
            dot += qr[d4 * 4 + 1] * kk4.y;
            dot += qr[d4 * 4 + 2] * kk4.z;
            dot += qr[d4 * 4 + 3] * kk4.w;
        }
        int dr = r1 - (m >> 3) + 7;
        int dc = c1 - (m & 7) + 7;
        dot += rs[dr * 15 + dc];
        s[m] = dot;
        mx = fmaxf(mx, dot);
    }
    float sum = 0.f;
#pragma unroll
    for (int m = 0; m < 64; m++) {
        s[m] = __expf(s[m] - mx);
        sum += s[m];
    }
    const float inv = 1.0f / sum;

    float accv[32];
#pragma unroll
    for (int d = 0; d < 32; d++) accv[d] = 0.f;
#pragma unroll
    for (int m = 0; m < 64; m++) {
        float p = s[m];
#pragma unroll
        for (int d4 = 0; d4 < 8; d4++) {
            float4 vv = *(const float4*)&vs_[m][d4 * 4];
            accv[d4 * 4 + 0] += p * vv.x;
            accv[d4 * 4 + 1] += p * vv.y;
            accv[d4 * 4 + 2] += p * vv.z;
            accv[d4 * 4 + 3] += p * vv.w;
        }
    }
    const size_t opix = (size_t)wi * 64 + n;
#pragma unroll
    for (int d4 = 0; d4 < 8; d4++) {
        float4 o;
        o.x = accv[d4 * 4 + 0] * inv;
        o.y = accv[d4 * 4 + 1] * inv;
        o.z = accv[d4 * 4 + 2] * inv;
        o.w = accv[d4 * 4 + 3] * inv;
        *(float4*)&out[opix * 192 + cb + d4 * 4] = o;
    }
}

// ============================================================================
extern "C" void kernel_launch(void* const* d_in, const int* in_sizes, int n_in,
                              void* d_out, int out_size)
{
    const float* x      = (const float*)d_in[0];
    const float* v_w    = (const float*)d_in[1];
    const float* v_b    = (const float*)d_in[2];
    const float* qk1_w  = (const float*)d_in[3];
    const float* qk1_b  = (const float*)d_in[4];
    const float* qk3_w1 = (const float*)d_in[5];
    const float* qk3_b1 = (const float*)d_in[6];
    const float* qk3_w2 = (const float*)d_in[7];
    const float* qk3_b2 = (const float*)d_in[8];
    const float* qk3_w3 = (const float*)d_in[9];
    const float* qk3_b3 = (const float*)d_in[10];
    const float* qk5_w1 = (const float*)d_in[11];
    const float* qk5_b1 = (const float*)d_in[12];
    const float* qk5_w2 = (const float*)d_in[13];
    const float* qk5_b2 = (const float*)d_in[14];
    const float* qk5_w3 = (const float*)d_in[15];
    const float* qk5_b3 = (const float*)d_in[16];
    const float* rpb    = (const float*)d_in[17];
    const float* proj_w = (const float*)d_in[18];
    const float* proj_b = (const float*)d_in[19];
    float* out = (float*)d_out;

    float *q, *k, *v, *ao, *t3a, *t3b, *t5a, *t5b;
    cudaGetSymbolAddress((void**)&q,   g_q);
    cudaGetSymbolAddress((void**)&k,   g_k);
    cudaGetSymbolAddress((void**)&v,   g_v);
    cudaGetSymbolAddress((void**)&ao,  g_ao);
    cudaGetSymbolAddress((void**)&t3a, g_t3a);
    cudaGetSymbolAddress((void**)&t3b, g_t3b);
    cudaGetSymbolAddress((void**)&t5a, g_t5a);
    cudaGetSymbolAddress((void**)&t5b, g_t5b);

    // v = conv1x1(x): N=192 in three 64-col blocks, stride 192
    conv_mma<1, 192, 64, 192, false, false><<<dim3(1024, 3), 256>>>(
        x, v_w, v_b, v, nullptr, 0);
    // qk1: N=128, split q/k at cbase 0
    conv_mma<1, 192, 64, 192, false, true><<<dim3(1024, 2), 256>>>(
        x, qk1_w, qk1_b, q, k, 0);
    // scale-3 branch
    conv_mma<3, 192, 32, 32, true, false><<<dim3(1024, 1), 256>>>(
        x, qk3_w1, qk3_b1, t3a, nullptr, 0);
    convB<1, 32, 2, true><<<1024, 128>>>(t3a, qk3_w2, qk3_b2, t3b, 32);
    conv_mma<3, 32, 64, 192, false, true><<<dim3(1024, 2), 256>>>(
        t3b, qk3_w3, qk3_b3, q, k, 64);
    // scale-5 branch
    conv_mma<5, 192, 16, 16, true, false><<<dim3(1024, 1), 256>>>(
        x, qk5_w1, qk5_b1, t5a, nullptr, 0);
    convB<1, 16, 4, true><<<1024, 64>>>(t5a, qk5_w2, qk5_b2, t5b, 16);
    conv_mma<5, 16, 64, 192, false, true><<<dim3(1024, 2), 256>>>(
        t5b, qk5_w3, qk5_b3, q, k, 128);
    // window attention
    attn_kernel<<<dim3(6, 4096), 64>>>(q, k, v, rpb, ao);
    // output projection straight into d_out
    conv_mma<1, 192, 64, 192, false, false><<<dim3(1024, 3), 256>>>(
        ao, proj_w, proj_b, out, nullptr, 0);
}

// round 6
// speedup vs baseline: 2.9249x; 1.3000x over previous
#include <cuda_runtime.h>
#include <cuda_fp16.h>
#include <cstdint>

#define NPIX (4 * 256 * 256)   // 262144 pixels
#define CDIM 192
#define SCALE 0.17677669529663689f

// ---------------- scratch (static device arrays; no runtime allocs) --------
__device__ __half g_xh [NPIX * CDIM];
__device__ __half g_q  [NPIX * CDIM];
__device__ __half g_k  [NPIX * CDIM];
__device__ __half g_v  [NPIX * CDIM];
__device__ __half g_ao [NPIX * CDIM];
__device__ __half g_t3a[NPIX * 32];
__device__ __half g_t3b[NPIX * 32];
__device__ __half g_t5a[NPIX * 16];
__device__ __half g_t5b[NPIX * 16];

__device__ __forceinline__ uint32_t pack_h2(float a, float b) {
    __half2 h = __floats2half2_rn(a, b);
    return *(uint32_t*)&h;
}

__device__ __forceinline__ void mma_f16_16x8x16(float* c, const uint32_t* a,
                                                const uint32_t* b) {
    asm volatile(
        "mma.sync.aligned.m16n8k16.row.col.f32.f16.f16.f32 "
        "{%0,%1,%2,%3}, {%4,%5,%6,%7}, {%8,%9}, {%0,%1,%2,%3};"
        : "+f"(c[0]), "+f"(c[1]), "+f"(c[2]), "+f"(c[3])
        : "r"(a[0]), "r"(a[1]), "r"(a[2]), "r"(a[3]), "r"(b[0]), "r"(b[1]));
}

// ---------------- fp32 -> fp16 prepass (x only) -----------------------------
__global__ __launch_bounds__(256)
void f2h_kernel(const float* __restrict__ in, __half* __restrict__ out)
{
    int i = blockIdx.x * blockDim.x + threadIdx.x;   // one uint4 (8 halves)
    float4 a = ((const float4*)in)[2 * i];
    float4 b = ((const float4*)in)[2 * i + 1];
    uint4 o;
    o.x = pack_h2(a.x, a.y); o.y = pack_h2(a.z, a.w);
    o.z = pack_h2(b.x, b.y); o.w = pack_h2(b.z, b.w);
    ((uint4*)out)[i] = o;
}

// ============================================================================
// Unified implicit-GEMM conv on fp16 mma.sync (fp32 accumulate), fp16 input.
// One CTA = one image row (256 output pixels) x BN output channels.
// A slab (256+2*PAD pixels x 16 cin) staged once per (kh, c0) as raw half2
// copies; kw taps are shifted SMEM reads. Weights (fp32) packed on the fly.
// grid = (1024 rows, Ncols/BN).
// ============================================================================
template <int KS, int CIN, int BN, int OSTR, bool RELU, bool SPLIT, typename OutT>
__global__ __launch_bounds__(256)
void conv_mma(const __half* __restrict__ X, const float* __restrict__ Wt,
              const float* __restrict__ bias, OutT* __restrict__ out0,
              OutT* __restrict__ out1, int cbase)
{
    constexpr int PAD = KS / 2;
    constexpr int AS_S = 264;          // A smem stride (uint32), %32 == 8
    constexpr int BS_S = KS * BN + 8;  // B smem stride, %32 in {8,24}
    __shared__ uint32_t As[8][AS_S];   // [k/2][pixel] half2 (k, k+1)
    __shared__ uint32_t Bs[8][BS_S];   // [k/2][kw*BN + cout]

    const int tid = threadIdx.x;
    const int lane = tid & 31, warp = tid >> 5;
    const int grp = lane >> 2, thr4 = lane & 3;

    constexpr int NW = (BN == 64) ? 2 : 1;
    constexpr int MW = 8 / NW;
    constexpr int WROWS = 256 / MW;          // 64 or 32
    constexpr int WCOLS = BN / NW;           // <= 32
    constexpr int MI = WROWS / 16;
    constexpr int NI = WCOLS / 8;
    const int mo = (NW == 2 ? (warp >> 1) : warp) * WROWS;
    const int no = (NW == 2 ? (warp & 1) : 0) * WCOLS;

    const int row = blockIdx.x;              // b*256 + h
    const int h = row & 255;
    const int pixbase = row << 8;
    const int n0 = blockIdx.y * BN;

    float acc[MI][NI][4];
#pragma unroll
    for (int i = 0; i < MI; i++)
#pragma unroll
        for (int j = 0; j < NI; j++)
#pragma unroll
            for (int r = 0; r < 4; r++) acc[i][j][r] = 0.0f;

    for (int kh = 0; kh < KS; kh++) {
        const int hs = h + kh - PAD;
        const bool vh = ((unsigned)hs < 256u);
        const int spix = (row - h + hs) << 8;
        for (int c0 = 0; c0 < CIN; c0 += 16) {
            // ---- stage A: (256 + 2*PAD) pixels x 16 cin (raw half copies) --
            {
                const int ws = tid - PAD;
                const bool ok = vh && ((unsigned)ws < 256u);
                const __half* src = X + (size_t)(spix + ws) * CIN + c0;
                uint4 u0 = make_uint4(0, 0, 0, 0), u1 = make_uint4(0, 0, 0, 0);
                if (ok) { u0 = *(const uint4*)src; u1 = *(const uint4*)(src + 8); }
                As[0][tid] = u0.x; As[1][tid] = u0.y;
                As[2][tid] = u0.z; As[3][tid] = u0.w;
                As[4][tid] = u1.x; As[5][tid] = u1.y;
                As[6][tid] = u1.z; As[7][tid] = u1.w;
                if (PAD > 0 && tid < 2 * PAD) {
                    const int p2 = 256 + tid;
                    const int ws2 = p2 - PAD;
                    const bool ok2 = vh && ((unsigned)ws2 < 256u);
                    const __half* src2 = X + (size_t)(spix + ws2) * CIN + c0;
                    uint4 w0 = make_uint4(0, 0, 0, 0), w1 = make_uint4(0, 0, 0, 0);
                    if (ok2) { w0 = *(const uint4*)src2; w1 = *(const uint4*)(src2 + 8); }
                    As[0][p2] = w0.x; As[1][p2] = w0.y;
                    As[2][p2] = w0.z; As[3][p2] = w0.w;
                    As[4][p2] = w1.x; As[5][p2] = w1.y;
                    As[6][p2] = w1.z; As[7][p2] = w1.w;
                }
            }
            // ---- stage B: BN couts x 8 k-pairs x KS kw taps (fp32 src) ----
            {
                constexpr int TOT = KS * BN * 8;
                for (int idx = tid; idx < TOT; idx += 256) {
                    int kw2 = idx / (BN * 8);
                    int rem = idx - kw2 * (BN * 8);
                    int j = rem >> 3, kp = rem & 7;
                    const float* wsrc = Wt + (size_t)(n0 + j) * (CIN * KS * KS)
                                        + (c0 + 2 * kp) * (KS * KS) + kh * KS + kw2;
                    Bs[kp][kw2 * BN + j] = pack_h2(wsrc[0], wsrc[KS * KS]);
                }
            }
            __syncthreads();

#pragma unroll
            for (int kw = 0; kw < KS; kw++) {
                uint32_t a[MI][4], b[NI][2];
#pragma unroll
                for (int mi = 0; mi < MI; mi++) {
                    int col = mo + mi * 16 + grp + kw;
                    a[mi][0] = As[thr4][col];
                    a[mi][1] = As[thr4][col + 8];
                    a[mi][2] = As[thr4 + 4][col];
                    a[mi][3] = As[thr4 + 4][col + 8];
                }
#pragma unroll
                for (int ni = 0; ni < NI; ni++) {
                    int bc = kw * BN + no + ni * 8 + grp;
                    b[ni][0] = Bs[thr4][bc];
                    b[ni][1] = Bs[thr4 + 4][bc];
                }
#pragma unroll
                for (int mi = 0; mi < MI; mi++)
#pragma unroll
                    for (int ni = 0; ni < NI; ni++)
                        mma_f16_16x8x16(acc[mi][ni], a[mi], b[ni]);
            }
            __syncthreads();
        }
    }

    // ---- epilogue ----
    OutT* dst;
    int cb, stride;
    if (SPLIT) {
        if (n0 < 64) { dst = out0; } else { dst = out1; }
        cb = cbase; stride = 192;
    } else { dst = out0; cb = n0; stride = OSTR; }

#pragma unroll
    for (int mi = 0; mi < MI; mi++) {
        size_t r0 = (size_t)(pixbase + mo + mi * 16 + grp);
        size_t r1 = r0 + 8;
#pragma unroll
        for (int ni = 0; ni < NI; ni++) {
            int colL = no + ni * 8 + 2 * thr4;
            float b0 = __ldg(&bias[n0 + colL]);
            float b1 = __ldg(&bias[n0 + colL + 1]);
            float v00 = acc[mi][ni][0] + b0, v01 = acc[mi][ni][1] + b1;
            float v10 = acc[mi][ni][2] + b0, v11 = acc[mi][ni][3] + b1;
            if (RELU) {
                v00 = v00 >= 0.f ? v00 : 0.2f * v00;
                v01 = v01 >= 0.f ? v01 : 0.2f * v01;
                v10 = v10 >= 0.f ? v10 : 0.2f * v10;
                v11 = v11 >= 0.f ? v11 : 0.2f * v11;
            }
            if (sizeof(OutT) == 2) {
                *(uint32_t*)&dst[r0 * stride + cb + colL] = pack_h2(v00, v01);
                *(uint32_t*)&dst[r1 * stride + cb + colL] = pack_h2(v10, v11);
            } else {
                *(float2*)&dst[r0 * stride + cb + colL] = make_float2(v00, v01);
                *(float2*)&dst[r1 * stride + cb + colL] = make_float2(v10, v11);
            }
        }
    }
}

// ============================================================================
// Window attention: fp16 in / fp16 out, fp32 compute.
// One 64-thread block per (window, head). grid = (6, 4096).
// ============================================================================
__global__ __launch_bounds__(64)
void attn_kernel(const __half* __restrict__ q, const __half* __restrict__ k,
                 const __half* __restrict__ v, const float* __restrict__ rpb,
                 __half* __restrict__ out)
{
    __shared__ float ks_[64][36];
    __shared__ float vs_[64][36];
    __shared__ float rs[225];

    const int hh = blockIdx.x;
    const int wi = blockIdx.y;
    const int n  = threadIdx.x;
    const int b  = wi >> 10;
    const int rem = wi & 1023;
    const int wh = rem >> 5, ww = rem & 31;
    const int r1 = n >> 3, c1 = n & 7;
    const int gh = wh * 8 + r1, gw = ww * 8 + c1;
    const size_t pix = (size_t)(b * 256 + gh) * 256 + gw;
    const int cb = hh * 32;

    for (int i = n; i < 225; i += 64) rs[i] = rpb[i * 6 + hh];

    float qr[32];
#pragma unroll
    for (int d8 = 0; d8 < 4; d8++) {
        uint4 ku = *(const uint4*)(k + pix * 192 + cb + d8 * 8);
        uint4 vu = *(const uint4*)(v + pix * 192 + cb + d8 * 8);
        uint4 qu = *(const uint4*)(q + pix * 192 + cb + d8 * 8);
        const __half2* kh2 = (const __half2*)&ku;
        const __half2* vh2 = (const __half2*)&vu;
        const __half2* qh2 = (const __half2*)&qu;
#pragma unroll
        for (int j = 0; j < 4; j++) {
            float2 kf = __half22float2(kh2[j]);
            float2 vf = __half22float2(vh2[j]);
            float2 qf = __half22float2(qh2[j]);
            ks_[n][d8 * 8 + 2 * j]     = kf.x;
            ks_[n][d8 * 8 + 2 * j + 1] = kf.y;
            vs_[n][d8 * 8 + 2 * j]     = vf.x;
            vs_[n][d8 * 8 + 2 * j + 1] = vf.y;
            qr[d8 * 8 + 2 * j]     = qf.x * SCALE;
            qr[d8 * 8 + 2 * j + 1] = qf.y * SCALE;
        }
    }
    __syncthreads();

    float s[64];
    float mx = -1e30f;
#pragma unroll
    for (int m = 0; m < 64; m++) {
        float dot = 0.f;
#pragma unroll
        for (int d4 = 0; d4 < 8; d4++) {
            float4 kk4 = *(const float4*)&ks_[m][d4 * 4];
            dot += qr[d4 * 4 + 0] * kk4.x;
            dot += qr[d4 * 4 + 1] * kk4.y;
            dot += qr[d4 * 4 + 2] * kk4.z;
            dot += qr[d4 * 4 + 3] * kk4.w;
        }
        int dr = r1 - (m >> 3) + 7;
        int dc = c1 - (m & 7) + 7;
        dot += rs[dr * 15 + dc];
        s[m] = dot;
        mx = fmaxf(mx, dot);
    }
    float sum = 0.f;
#pragma unroll
    for (int m = 0; m < 64; m++) {
        s[m] = __expf(s[m] - mx);
        sum += s[m];
    }
    const float inv = 1.0f / sum;

    float accv[32];
#pragma unroll
    for (int d = 0; d < 32; d++) accv[d] = 0.f;
#pragma unroll
    for (int m = 0; m < 64; m++) {
        float p = s[m];
#pragma unroll
        for (int d4 = 0; d4 < 8; d4++) {
            float4 vv = *(const float4*)&vs_[m][d4 * 4];
            accv[d4 * 4 + 0] += p * vv.x;
            accv[d4 * 4 + 1] += p * vv.y;
            accv[d4 * 4 + 2] += p * vv.z;
            accv[d4 * 4 + 3] += p * vv.w;
        }
    }
    const size_t opix = (size_t)wi * 64 + n;
    __half* op = out + opix * 192 + cb;
#pragma unroll
    for (int d8 = 0; d8 < 4; d8++) {
        uint4 o;
        o.x = pack_h2(accv[d8 * 8 + 0] * inv, accv[d8 * 8 + 1] * inv);
        o.y = pack_h2(accv[d8 * 8 + 2] * inv, accv[d8 * 8 + 3] * inv);
        o.z = pack_h2(accv[d8 * 8 + 4] * inv, accv[d8 * 8 + 5] * inv);
        o.w = pack_h2(accv[d8 * 8 + 6] * inv, accv[d8 * 8 + 7] * inv);
        *(uint4*)(op + d8 * 8) = o;
    }
}

// ============================================================================
extern "C" void kernel_launch(void* const* d_in, const int* in_sizes, int n_in,
                              void* d_out, int out_size)
{
    const float* x      = (const float*)d_in[0];
    const float* v_w    = (const float*)d_in[1];
    const float* v_b    = (const float*)d_in[2];
    const float* qk1_w  = (const float*)d_in[3];
    const float* qk1_b  = (const float*)d_in[4];
    const float* qk3_w1 = (const float*)d_in[5];
    const float* qk3_b1 = (const float*)d_in[6];
    const float* qk3_w2 = (const float*)d_in[7];
    const float* qk3_b2 = (const float*)d_in[8];
    const float* qk3_w3 = (const float*)d_in[9];
    const float* qk3_b3 = (const float*)d_in[10];
    const float* qk5_w1 = (const float*)d_in[11];
    const float* qk5_b1 = (const float*)d_in[12];
    const float* qk5_w2 = (const float*)d_in[13];
    const float* qk5_b2 = (const float*)d_in[14];
    const float* qk5_w3 = (const float*)d_in[15];
    const float* qk5_b3 = (const float*)d_in[16];
    const float* rpb    = (const float*)d_in[17];
    const float* proj_w = (const float*)d_in[18];
    const float* proj_b = (const float*)d_in[19];
    float* out = (float*)d_out;

    __half *xh, *q, *k, *v, *ao, *t3a, *t3b, *t5a, *t5b;
    cudaGetSymbolAddress((void**)&xh,  g_xh);
    cudaGetSymbolAddress((void**)&q,   g_q);
    cudaGetSymbolAddress((void**)&k,   g_k);
    cudaGetSymbolAddress((void**)&v,   g_v);
    cudaGetSymbolAddress((void**)&ao,  g_ao);
    cudaGetSymbolAddress((void**)&t3a, g_t3a);
    cudaGetSymbolAddress((void**)&t3b, g_t3b);
    cudaGetSymbolAddress((void**)&t5a, g_t5a);
    cudaGetSymbolAddress((void**)&t5b, g_t5b);

    // prepass: x -> fp16
    f2h_kernel<<<NPIX * CDIM / (256 * 8), 256>>>(x, xh);

    // v = conv1x1(x): N=192 in three 64-col blocks, stride 192
    conv_mma<1, 192, 64, 192, false, false, __half><<<dim3(1024, 3), 256>>>(
        xh, v_w, v_b, v, nullptr, 0);
    // qk1: N=128, split q/k at cbase 0
    conv_mma<1, 192, 64, 192, false, true, __half><<<dim3(1024, 2), 256>>>(
        xh, qk1_w, qk1_b, q, k, 0);
    // scale-3 branch
    conv_mma<3, 192, 32, 32, true, false, __half><<<dim3(1024, 1), 256>>>(
        xh, qk3_w1, qk3_b1, t3a, nullptr, 0);
    conv_mma<1, 32, 32, 32, true, false, __half><<<dim3(1024, 1), 256>>>(
        t3a, qk3_w2, qk3_b2, t3b, nullptr, 0);
    conv_mma<3, 32, 64, 192, false, true, __half><<<dim3(1024, 2), 256>>>(
        t3b, qk3_w3, qk3_b3, q, k, 64);
    // scale-5 branch
    conv_mma<5, 192, 16, 16, true, false, __half><<<dim3(1024, 1), 256>>>(
        xh, qk5_w1, qk5_b1, t5a, nullptr, 0);
    conv_mma<1, 16, 16, 16, true, false, __half><<<dim3(1024, 1), 256>>>(
        t5a, qk5_w2, qk5_b2, t5b, nullptr, 0);
    conv_mma<5, 16, 64, 192, false, true, __half><<<dim3(1024, 2), 256>>>(
        t5b, qk5_w3, qk5_b3, q, k, 128);
    // window attention (fp16 in/out)
    attn_kernel<<<dim3(6, 4096), 64>>>(q, k, v, rpb, ao);
    // output projection straight into d_out (fp32)
    conv_mma<1, 192, 64, 192, false, false, float><<<dim3(1024, 3), 256>>>(
        ao, proj_w, proj_b, out, nullptr, 0);
}